// round 14
// baseline (speedup 1.0000x reference)
#include <cuda_runtime.h>
#include <cuda_bf16.h>
#include <cstdint>
#include <cstddef>

#define LL   4096
#define CC   32
#define NCH  128
#define BHT  16
#define SDK  132
#define OUT_ELEMS  ((size_t)BHT * LL * 128)
#define S_ELEMS    ((size_t)BHT * 128 * 128)

typedef unsigned long long ull;

// g_wqT: [bh][ch][128][64] k-major: cols 0..31 = w rows, 32..63 = q-hat rows
// g_kR : [bh][ch][32][128] k-hat row-major
// g_at2: [bh][ch][32][32]  masked attn, chunks swizzled (j4 ^ (i&7))
// g_u2 : [bh][slice8][ch][32][16]
__device__ float g_wqT[(size_t)BHT * NCH * 128 * 64];
__device__ float g_kR [(size_t)BHT * NCH * 32 * 128];
__device__ float g_at2[(size_t)BHT * NCH * 32 * 32];
__device__ float g_u2 [(size_t)BHT * 8 * NCH * 32 * 16];

__device__ __forceinline__ float dot4(float4 a, float4 b) {
    return a.x * b.x + a.y * b.y + a.z * b.z + a.w * b.w;
}
__device__ __forceinline__ ull pk1(float x) {
    ull r; asm("mov.b64 %0,{%1,%1};" : "=l"(r) : "f"(x)); return r;
}
__device__ __forceinline__ void fm2(ull& a, ull b, ull c) {
    asm("fma.rn.f32x2 %0,%1,%2,%3;" : "=l"(a) : "l"(b), "l"(c), "l"(a));
}
__device__ __forceinline__ ull ad2r(ull a, ull b) {
    ull r; asm("add.rn.f32x2 %0,%1,%2;" : "=l"(r) : "l"(a), "l"(b)); return r;
}
__device__ __forceinline__ float2 upk(ull a) {
    float2 f; asm("mov.b64 {%0,%1},%2;" : "=f"(f.x), "=f"(f.y) : "l"(a)); return f;
}
__device__ __forceinline__ uint32_t s2u(const void* p) {
    return (uint32_t)__cvta_generic_to_shared(p);
}
__device__ __forceinline__ void mbar_init(uint32_t m, uint32_t c) {
    asm volatile("mbarrier.init.shared.b64 [%0], %1;" :: "r"(m), "r"(c) : "memory");
}
__device__ __forceinline__ void mbar_expect(uint32_t m, uint32_t b) {
    asm volatile("mbarrier.arrive.expect_tx.shared.b64 _, [%0], %1;" :: "r"(m), "r"(b) : "memory");
}
__device__ __forceinline__ void mbar_wait(uint32_t m, uint32_t p) {
    asm volatile(
        "{\n\t.reg .pred P;\n\tW%=:\n\t"
        "mbarrier.try_wait.parity.acquire.cta.shared::cta.b64 P, [%0], %1, 0x989680;\n\t"
        "@P bra D%=;\n\tbra W%=;\n\tD%=:\n\t}" :: "r"(m), "r"(p) : "memory");
}
__device__ __forceinline__ void bulkcp(uint32_t d, const void* s, uint32_t b, uint32_t m) {
    asm volatile("cp.async.bulk.shared::cta.global.mbarrier::complete_tx::bytes [%0], [%1], %2, [%3];"
        :: "r"(d), "l"(s), "r"(b), "r"(m) : "memory");
}

// =====================================================================
// Phase 1: grid (NCH, BHT), 256 threads.
// =====================================================================
__global__ __launch_bounds__(256) void phase1_kernel(
    const float* __restrict__ gq, const float* __restrict__ gk,
    const float* __restrict__ gv, const float* __restrict__ gbeta)
{
    extern __shared__ float sm[];
    float* sq    = sm;
    float* sk    = sm + CC * SDK;
    float* sv    = sm + 2 * CC * SDK;
    float* sA    = sm + 3 * CC * SDK;
    float* sbeta = sA + CC * (CC + 1);
    float* sqs   = sbeta + CC;
    float* sks   = sqs + CC;

    const int t  = threadIdx.x;
    const int ch = blockIdx.x;
    const int bh = blockIdx.y;
    const size_t gbase = ((size_t)bh * LL + (size_t)ch * CC) * 128;

    {
        const float4* q4 = (const float4*)(gq + gbase);
        const float4* k4 = (const float4*)(gk + gbase);
        const float4* v4 = (const float4*)(gv + gbase);
        for (int idx = t; idx < 1024; idx += 256) {
            int r = idx >> 5, c4 = idx & 31;
            ((float4*)(sq + r * SDK))[c4] = q4[idx];
            ((float4*)(sk + r * SDK))[c4] = k4[idx];
            ((float4*)(sv + r * SDK))[c4] = v4[idx];
        }
    }
    if (t < CC) sbeta[t] = gbeta[(size_t)bh * LL + (size_t)ch * CC + t];
    __syncthreads();

    {   // row l2 norms
        int row = t >> 3, seg = t & 7;
        const float4* qr = (const float4*)(sq + row * SDK) + seg * 4;
        const float4* kr = (const float4*)(sk + row * SDK) + seg * 4;
        float s2q = 0.f, s2k = 0.f;
        #pragma unroll
        for (int i2 = 0; i2 < 4; i2++) {
            float4 a = qr[i2]; s2q += dot4(a, a);
            float4 b = kr[i2]; s2k += dot4(b, b);
        }
        #pragma unroll
        for (int off = 4; off; off >>= 1) {
            s2q += __shfl_down_sync(0xffffffffu, s2q, off, 8);
            s2k += __shfl_down_sync(0xffffffffu, s2k, off, 8);
        }
        if (seg == 0) { sqs[row] = rsqrtf(s2q + 1e-6f); sks[row] = rsqrtf(s2k + 1e-6f); }
    }
    __syncthreads();
    {
        int row = t >> 3, seg = t & 7;
        float a = sqs[row], b = sks[row];
        float4* qr = (float4*)(sq + row * SDK) + seg * 4;
        float4* kr = (float4*)(sk + row * SDK) + seg * 4;
        #pragma unroll
        for (int i2 = 0; i2 < 4; i2++) {
            float4 x = qr[i2]; x.x *= a; x.y *= a; x.z *= a; x.w *= a; qr[i2] = x;
            float4 y = kr[i2]; y.x *= b; y.y *= b; y.z *= b; y.w *= b; kr[i2] = y;
        }
    }
    __syncthreads();

    const size_t wqb   = ((size_t)(bh * NCH + ch)) * 8192;
    const size_t krb   = ((size_t)(bh * NCH + ch)) * 4096;
    const size_t abase = ((size_t)(bh * NCH + ch)) * 1024;

    {   // q-hat (k-major) -> g_wqT cols 32..63
        int d = t >> 1, half = t & 1, i0q = half * 16;
        #pragma unroll
        for (int ii = 0; ii < 16; ii += 4) {
            float4 a = make_float4(sq[(i0q + ii) * SDK + d], sq[(i0q + ii + 1) * SDK + d],
                                   sq[(i0q + ii + 2) * SDK + d], sq[(i0q + ii + 3) * SDK + d]);
            *(float4*)(g_wqT + wqb + (size_t)d * 64 + 32 + i0q + ii) = a;
        }
    }
    for (int idx = t; idx < 1024; idx += 256) {
        int r = idx >> 5, c4 = idx & 31;
        *(float4*)(g_kR + krb + (size_t)r * 128 + (c4 << 2)) =
            *(const float4*)(sk + r * SDK + (c4 << 2));
    }

    {   // dots (f32x2), stride-16 tile: rows {ti,ti+16} x cols {tj,tj+16}
        int ti = t >> 4, tj = t & 15;
        int iA = ti, iB = ti + 16;
        int jA = tj, jB = tj + 16;
        ull pkkAA = 0, pkkAB = 0, pkkBA = 0, pkkBB = 0;
        ull pqkAA = 0, pqkAB = 0, pqkBA = 0, pqkBB = 0;
        const ulonglong2* kiA = (const ulonglong2*)(sk + iA * SDK);
        const ulonglong2* kiB = (const ulonglong2*)(sk + iB * SDK);
        const ulonglong2* kjA = (const ulonglong2*)(sk + jA * SDK);
        const ulonglong2* kjB = (const ulonglong2*)(sk + jB * SDK);
        const ulonglong2* qiA = (const ulonglong2*)(sq + iA * SDK);
        const ulonglong2* qiB = (const ulonglong2*)(sq + iB * SDK);
        #pragma unroll 8
        for (int d4 = 0; d4 < 32; d4++) {
            ulonglong2 A0 = kiA[d4], A1 = kiB[d4];
            ulonglong2 B0 = kjA[d4], B1 = kjB[d4];
            ulonglong2 C0 = qiA[d4], C1 = qiB[d4];
            fm2(pkkAA, A0.x, B0.x); fm2(pkkAA, A0.y, B0.y);
            fm2(pkkAB, A0.x, B1.x); fm2(pkkAB, A0.y, B1.y);
            fm2(pkkBA, A1.x, B0.x); fm2(pkkBA, A1.y, B0.y);
            fm2(pkkBB, A1.x, B1.x); fm2(pkkBB, A1.y, B1.y);
            fm2(pqkAA, C0.x, B0.x); fm2(pqkAA, C0.y, B0.y);
            fm2(pqkAB, C0.x, B1.x); fm2(pqkAB, C0.y, B1.y);
            fm2(pqkBA, C1.x, B0.x); fm2(pqkBA, C1.y, B0.y);
            fm2(pqkBB, C1.x, B1.x); fm2(pqkBB, C1.y, B1.y);
        }
        float2 e;
        e = upk(pkkAA); float dkkAA = e.x + e.y;
        e = upk(pkkAB); float dkkAB = e.x + e.y;
        e = upk(pkkBA); float dkkBA = e.x + e.y;
        e = upk(pkkBB); float dkkBB = e.x + e.y;
        e = upk(pqkAA); float dqkAA = e.x + e.y;
        e = upk(pqkAB); float dqkAB = e.x + e.y;
        e = upk(pqkBA); float dqkBA = e.x + e.y;
        e = upk(pqkBB); float dqkBB = e.x + e.y;
        float biA = sbeta[iA], biB = sbeta[iB];
        sA[iA * 33 + jA] = (iA > jA) ? -biA * dkkAA : 0.f;
        sA[iA * 33 + jB] = (iA > jB) ? -biA * dkkAB : 0.f;
        sA[iB * 33 + jA] = (iB > jA) ? -biB * dkkBA : 0.f;
        sA[iB * 33 + jB] = (iB > jB) ? -biB * dkkBB : 0.f;
        #define ATW(ii, jj, val) g_at2[abase + (size_t)(ii) * 32 + \
            (size_t)(((((jj) >> 2) ^ ((ii) & 7)) << 2) + ((jj) & 3))] = (val)
        ATW(iA, jA, (iA >= jA) ? dqkAA : 0.f);
        ATW(iA, jB, (iA >= jB) ? dqkAB : 0.f);
        ATW(iB, jA, (iB >= jA) ? dqkBA : 0.f);
        ATW(iB, jB, (iB >= jB) ? dqkBB : 0.f);
        #undef ATW
    }
    __syncthreads();

    // forward substitution (exact reference order), warp 0
    if (t < 32) {
        int lane = t;
        for (int i = 1; i < CC; i++) {
            float s = 0.f;
            if (lane < i) {
                for (int kk = lane + 1; kk < i; kk++)
                    s += sA[i * 33 + kk] * sA[kk * 33 + lane];
            }
            __syncwarp();
            if (lane < i) sA[i * 33 + lane] += s;
            __syncwarp();
        }
        sA[lane * 33 + lane] = 1.0f;
    }
    __syncthreads();

    for (int idx = t; idx < 1024; idx += 256) {
        int i = idx >> 5, j = idx & 31;
        sA[i * 33 + j] *= sbeta[j];
    }
    __syncthreads();

    // u = Abeta @ v ; w = Abeta @ k-hat
    // Each thread: rows i0,i0+1 x cols {cA..cA+3} and {cB..cB+3} (16B lane stride).
    {
        int p = t >> 4, dseg = t & 15;
        int i0 = 2 * p;
        int cA = dseg << 2;
        int cB = 64 + (dseg << 2);
        ulonglong2 u0a = {0,0}, u0b = {0,0}, u1a = {0,0}, u1b = {0,0};
        ulonglong2 w0a = {0,0}, w0b = {0,0}, w1a = {0,0}, w1b = {0,0};
        #pragma unroll 4
        for (int j = 0; j < CC; j++) {
            ull A0 = pk1(sA[i0 * 33 + j]);
            ull A1 = pk1(sA[(i0 + 1) * 33 + j]);
            ulonglong2 va = *(const ulonglong2*)(sv + j * SDK + cA);
            ulonglong2 vb = *(const ulonglong2*)(sv + j * SDK + cB);
            ulonglong2 ka = *(const ulonglong2*)(sk + j * SDK + cA);
            ulonglong2 kb = *(const ulonglong2*)(sk + j * SDK + cB);
            fm2(u0a.x, A0, va.x); fm2(u0a.y, A0, va.y);
            fm2(u0b.x, A0, vb.x); fm2(u0b.y, A0, vb.y);
            fm2(u1a.x, A1, va.x); fm2(u1a.y, A1, va.y);
            fm2(u1b.x, A1, vb.x); fm2(u1b.y, A1, vb.y);
            fm2(w0a.x, A0, ka.x); fm2(w0a.y, A0, ka.y);
            fm2(w0b.x, A0, kb.x); fm2(w0b.y, A0, kb.y);
            fm2(w1a.x, A1, ka.x); fm2(w1a.y, A1, ka.y);
            fm2(w1b.x, A1, kb.x); fm2(w1b.y, A1, kb.y);
        }
        int slA = dseg >> 2, offA = (dseg & 3) << 2;
        size_t ubA = (((size_t)(bh * 8 + slA)) * NCH + ch) * 512;
        size_t ubB = (((size_t)(bh * 8 + 4 + slA)) * NCH + ch) * 512;
        *(ulonglong2*)(g_u2 + ubA + (size_t)i0 * 16 + offA)       = u0a;
        *(ulonglong2*)(g_u2 + ubB + (size_t)i0 * 16 + offA)       = u0b;
        *(ulonglong2*)(g_u2 + ubA + (size_t)(i0 + 1) * 16 + offA) = u1a;
        *(ulonglong2*)(g_u2 + ubB + (size_t)(i0 + 1) * 16 + offA) = u1b;
        float wA0[4], wB0[4], wA1[4], wB1[4];
        float2 e;
        e = upk(w0a.x); wA0[0] = e.x; wA0[1] = e.y;
        e = upk(w0a.y); wA0[2] = e.x; wA0[3] = e.y;
        e = upk(w0b.x); wB0[0] = e.x; wB0[1] = e.y;
        e = upk(w0b.y); wB0[2] = e.x; wB0[3] = e.y;
        e = upk(w1a.x); wA1[0] = e.x; wA1[1] = e.y;
        e = upk(w1a.y); wA1[2] = e.x; wA1[3] = e.y;
        e = upk(w1b.x); wB1[0] = e.x; wB1[1] = e.y;
        e = upk(w1b.y); wB1[2] = e.x; wB1[3] = e.y;
        #pragma unroll
        for (int dd = 0; dd < 4; dd++) {
            *(float2*)(g_wqT + wqb + (size_t)(cA + dd) * 64 + i0) =
                make_float2(wA0[dd], wA1[dd]);
            *(float2*)(g_wqT + wqb + (size_t)(cB + dd) * 64 + i0) =
                make_float2(wB0[dd], wB1[dd]);
        }
    }
}

// =====================================================================
// Phase 2: sequential scan, dv split 8x16. grid (8, BHT), 256 threads.
// =====================================================================
#define BUF_F   13824
#define OFF_K   8192
#define OFF_AT  12288
#define OFF_U   13312
#define TX_BYTES 55296u

__global__ __launch_bounds__(256) void phase2_kernel(
    float* __restrict__ out, float* __restrict__ Sout)
{
    extern __shared__ float sm[];
    float* sS   = sm + 4;
    float* po   = sm + 4 + 2048;
    float* bufs = sm + 4 + 2048 + 512;

    const int t = threadIdx.x;
    const int slice = blockIdx.x;
    const int bh    = blockIdx.y;
    const int c0    = slice * 16;

    const int lane = t & 31, warp = t >> 5;
    const int tl = lane & 7, kg = lane >> 3;
    const int tile = warp * 8 + tl;
    const int tr = tile & 15, tc = tile >> 4;
    const int i0 = tr << 2;
    const int cb4 = tc << 2;

    const uint32_t mb0 = s2u(sm), mb1 = mb0 + 8;

    for (int idx = t; idx < 2048; idx += 256) sS[idx] = 0.f;
    if (t == 0) { mbar_init(mb0, 1); mbar_init(mb1, 1); }
    __syncthreads();

    const size_t cb0 = (size_t)bh * NCH;
    const size_t ublk = ((size_t)(bh * 8 + slice)) * NCH;
    if (t == 0) {
        mbar_expect(mb0, TX_BYTES);
        bulkcp(s2u(bufs),           g_wqT + cb0 * 8192, 32768, mb0);
        bulkcp(s2u(bufs + OFF_K),   g_kR  + cb0 * 4096, 16384, mb0);
        bulkcp(s2u(bufs + OFF_AT),  g_at2 + cb0 * 1024, 4096, mb0);
        bulkcp(s2u(bufs + OFF_U),   g_u2  + ublk * 512, 2048, mb0);
    }

    for (int ch = 0; ch < NCH; ch++) {
        const int b = ch & 1;
        float* B  = bufs + b * BUF_F;
        float* bu = B + OFF_U;

        __syncthreads();
        if (t == 0 && ch + 1 < NCH) {
            uint32_t mb = b ? mb0 : mb1;
            float* B2 = bufs + (b ^ 1) * BUF_F;
            const size_t cb = cb0 + ch + 1;
            mbar_expect(mb, TX_BYTES);
            bulkcp(s2u(B2),          g_wqT + cb * 8192, 32768, mb);
            bulkcp(s2u(B2 + OFF_K),  g_kR  + cb * 4096, 16384, mb);
            bulkcp(s2u(B2 + OFF_AT), g_at2 + cb * 1024, 4096, mb);
            bulkcp(s2u(B2 + OFF_U),  g_u2  + (ublk + ch + 1) * 512, 2048, mb);
        }
        mbar_wait(b ? mb1 : mb0, (ch >> 1) & 1);

        // ---- P = [w;q]@S : 4x4 tile, k-split-4 ----
        ull a00 = 0, a01 = 0, a10 = 0, a11 = 0, a20 = 0, a21 = 0, a30 = 0, a31 = 0;
        {
            const float* wp = B + (kg << 5) * 64 + i0;
            const float* sbase = sS + (kg << 5) * 16;
            #pragma unroll
            for (int k = 0; k < 32; k++) {
                float4 w4 = *(const float4*)(wp + k * 64);
                const int phys = ((tc ^ ((k >> 2) & 3) ^ kg) << 2);
                ulonglong2 s2 = *(const ulonglong2*)(sbase + k * 16 + phys);
                fm2(a00, pk1(w4.x), s2.x); fm2(a01, pk1(w4.x), s2.y);
                fm2(a10, pk1(w4.y), s2.x); fm2(a11, pk1(w4.y), s2.y);
                fm2(a20, pk1(w4.z), s2.x); fm2(a21, pk1(w4.z), s2.y);
                fm2(a30, pk1(w4.w), s2.x); fm2(a31, pk1(w4.w), s2.y);
            }
        }
        #pragma unroll
        for (int m = 8; m <= 16; m <<= 1) {
            a00 = ad2r(a00, __shfl_xor_sync(0xffffffffu, a00, m));
            a01 = ad2r(a01, __shfl_xor_sync(0xffffffffu, a01, m));
            a10 = ad2r(a10, __shfl_xor_sync(0xffffffffu, a10, m));
            a11 = ad2r(a11, __shfl_xor_sync(0xffffffffu, a11, m));
            a20 = ad2r(a20, __shfl_xor_sync(0xffffffffu, a20, m));
            a21 = ad2r(a21, __shfl_xor_sync(0xffffffffu, a21, m));
            a30 = ad2r(a30, __shfl_xor_sync(0xffffffffu, a30, m));
            a31 = ad2r(a31, __shfl_xor_sync(0xffffffffu, a31, m));
        }
        {   // distributed tail: lane kg handles row i0+kg
            ull ax, ay;
            if (kg == 0)      { ax = a00; ay = a01; }
            else if (kg == 1) { ax = a10; ay = a11; }
            else if (kg == 2) { ax = a20; ay = a21; }
            else              { ax = a30; ay = a31; }
            float2 lo = upk(ax), hi = upk(ay);
            const int row = i0 + kg;
            if (tr < 8) {
                float* up = bu + row * 16 + cb4;
                float4 u0 = *(const float4*)up;
                u0.x -= lo.x; u0.y -= lo.y; u0.z -= hi.x; u0.w -= hi.y;
                *(float4*)up = u0;
            } else {
                *(float4*)(po + (row - 32) * 16 + cb4) =
                    make_float4(lo.x, lo.y, hi.x, hi.y);
            }
        }
        __syncthreads();

        if (t < 128) {
            const int rt = t >> 2, ct = t & 3;
            const int rb = rt << 2;
            const int physc = ((ct ^ ((rt ^ (rt >> 3)) & 3)) << 2);
            float* sp0 = sS + rb * 16 + physc;
            ulonglong2 s0 = *(const ulonglong2*)(sp0);
            ulonglong2 s1 = *(const ulonglong2*)(sp0 + 16);
            ulonglong2 s2v = *(const ulonglong2*)(sp0 + 32);
            ulonglong2 s3 = *(const ulonglong2*)(sp0 + 48);
            const float* kp = B + OFF_K + rb;
            const float* up2 = bu + (ct << 2);
            #pragma unroll 8
            for (int j = 0; j < 32; j++) {
                float4 k4 = *(const float4*)kp;
                ulonglong2 u2 = *(const ulonglong2*)up2;
                fm2(s0.x,  pk1(k4.x), u2.x); fm2(s0.y,  pk1(k4.x), u2.y);
                fm2(s1.x,  pk1(k4.y), u2.x); fm2(s1.y,  pk1(k4.y), u2.y);
                fm2(s2v.x, pk1(k4.z), u2.x); fm2(s2v.y, pk1(k4.z), u2.y);
                fm2(s3.x,  pk1(k4.w), u2.x); fm2(s3.y,  pk1(k4.w), u2.y);
                kp += 128; up2 += 16;
            }
            *(ulonglong2*)(sp0)      = s0;
            *(ulonglong2*)(sp0 + 16) = s1;
            *(ulonglong2*)(sp0 + 32) = s2v;
            *(ulonglong2*)(sp0 + 48) = s3;
        } else {
            const int ii2 = (t - 128) >> 2, cq = t & 3;
            const int asw = ii2 & 7;
            ulonglong2 acc = *(const ulonglong2*)(po + ii2 * 16 + (cq << 2));
            const float* atr = B + OFF_AT + ii2 * 32;
            const float* Up = bu + (cq << 2);
            #pragma unroll
            for (int j4 = 0; j4 < 8; j4++) {
                float4 a4 = *(const float4*)(atr + ((j4 ^ asw) << 2));
                const float* u0p = Up + (j4 << 6);
                ulonglong2 U0 = *(const ulonglong2*)(u0p);
                ulonglong2 U1 = *(const ulonglong2*)(u0p + 16);
                ulonglong2 U2 = *(const ulonglong2*)(u0p + 32);
                ulonglong2 U3 = *(const ulonglong2*)(u0p + 48);
                fm2(acc.x, pk1(a4.x), U0.x); fm2(acc.y, pk1(a4.x), U0.y);
                fm2(acc.x, pk1(a4.y), U1.x); fm2(acc.y, pk1(a4.y), U1.y);
                fm2(acc.x, pk1(a4.z), U2.x); fm2(acc.y, pk1(a4.z), U2.y);
                fm2(acc.x, pk1(a4.w), U3.x); fm2(acc.y, pk1(a4.w), U3.y);
            }
            float2 f0 = upk(acc.x), f1 = upk(acc.y);
            size_t off = ((size_t)bh * LL + (size_t)ch * CC + ii2) * 128 + c0 + (cq << 2);
            *(float4*)(out + off) = make_float4(f0.x, f0.y, f1.x, f1.y);
        }
    }

    if (Sout != nullptr) {
        __syncthreads();
        size_t sb = (size_t)bh * 128 * 128;
        for (int idx = t; idx < 2048; idx += 256) {
            int r = idx >> 4, c = idx & 15;
            int phys = ((((c >> 2) ^ ((r >> 2) & 3) ^ ((r >> 5) & 3)) & 3) << 2) + (c & 3);
            Sout[sb + (size_t)r * 128 + c0 + c] = sS[r * 16 + phys];
        }
    }
}

// =====================================================================
#define P1_SMEM ((3 * CC * SDK + CC * (CC + 1) + 3 * CC) * (int)sizeof(float))
#define P2_SMEM ((4 + 2048 + 512 + 2 * BUF_F) * (int)sizeof(float))

extern "C" void kernel_launch(void* const* d_in, const int* in_sizes, int n_in,
                              void* d_out, int out_size)
{
    const float* q    = (const float*)d_in[0];
    const float* k    = (const float*)d_in[1];
    const float* v    = (const float*)d_in[2];
    const float* beta = (const float*)d_in[3];
    float* out = (float*)d_out;
    float* Sout = ((size_t)out_size >= OUT_ELEMS + S_ELEMS) ? (out + OUT_ELEMS) : nullptr;

    cudaFuncSetAttribute(phase1_kernel, cudaFuncAttributeMaxDynamicSharedMemorySize, P1_SMEM);
    cudaFuncSetAttribute(phase2_kernel, cudaFuncAttributeMaxDynamicSharedMemorySize, P2_SMEM);

    phase1_kernel<<<dim3(NCH, BHT), 256, P1_SMEM>>>(q, k, v, beta);
    phase2_kernel<<<dim3(8, BHT), 256, P2_SMEM>>>(out, Sout);
}

// round 15
// speedup vs baseline: 1.6313x; 1.6313x over previous
#include <cuda_runtime.h>
#include <cuda_bf16.h>
#include <cstdint>
#include <cstddef>

#define LL   4096
#define CC   32
#define NCH  128
#define BHT  16
#define SDK  132
#define OUT_ELEMS  ((size_t)BHT * LL * 128)
#define S_ELEMS    ((size_t)BHT * 128 * 128)

typedef unsigned long long ull;

// g_wqT: [bh][ch][128][64] k-major: cols 0..31 = w rows, 32..63 = q-hat rows
// g_kR : [bh][ch][32][128] k-hat row-major
// g_at2: [bh][ch][32][32]  masked attn, chunks swizzled (j4 ^ (i&7))
// g_u2 : [bh][slice8][ch][32][16]
__device__ float g_wqT[(size_t)BHT * NCH * 128 * 64];
__device__ float g_kR [(size_t)BHT * NCH * 32 * 128];
__device__ float g_at2[(size_t)BHT * NCH * 32 * 32];
__device__ float g_u2 [(size_t)BHT * 8 * NCH * 32 * 16];

__device__ __forceinline__ float dot4(float4 a, float4 b) {
    return a.x * b.x + a.y * b.y + a.z * b.z + a.w * b.w;
}
__device__ __forceinline__ ull pk1(float x) {
    ull r; asm("mov.b64 %0,{%1,%1};" : "=l"(r) : "f"(x)); return r;
}
__device__ __forceinline__ void fm2(ull& a, ull b, ull c) {
    asm("fma.rn.f32x2 %0,%1,%2,%3;" : "=l"(a) : "l"(b), "l"(c), "l"(a));
}
__device__ __forceinline__ ull ad2r(ull a, ull b) {
    ull r; asm("add.rn.f32x2 %0,%1,%2;" : "=l"(r) : "l"(a), "l"(b)); return r;
}
__device__ __forceinline__ float2 upk(ull a) {
    float2 f; asm("mov.b64 {%0,%1},%2;" : "=f"(f.x), "=f"(f.y) : "l"(a)); return f;
}
__device__ __forceinline__ uint32_t s2u(const void* p) {
    return (uint32_t)__cvta_generic_to_shared(p);
}
__device__ __forceinline__ void mbar_init(uint32_t m, uint32_t c) {
    asm volatile("mbarrier.init.shared.b64 [%0], %1;" :: "r"(m), "r"(c) : "memory");
}
__device__ __forceinline__ void mbar_expect(uint32_t m, uint32_t b) {
    asm volatile("mbarrier.arrive.expect_tx.shared.b64 _, [%0], %1;" :: "r"(m), "r"(b) : "memory");
}
__device__ __forceinline__ void mbar_wait(uint32_t m, uint32_t p) {
    asm volatile(
        "{\n\t.reg .pred P;\n\tW%=:\n\t"
        "mbarrier.try_wait.parity.acquire.cta.shared::cta.b64 P, [%0], %1, 0x989680;\n\t"
        "@P bra D%=;\n\tbra W%=;\n\tD%=:\n\t}" :: "r"(m), "r"(p) : "memory");
}
__device__ __forceinline__ void bulkcp(uint32_t d, const void* s, uint32_t b, uint32_t m) {
    asm volatile("cp.async.bulk.shared::cta.global.mbarrier::complete_tx::bytes [%0], [%1], %2, [%3];"
        :: "r"(d), "l"(s), "r"(b), "r"(m) : "memory");
}

// =====================================================================
// Phase 1: grid (NCH, BHT), 256 threads.
// =====================================================================
__global__ __launch_bounds__(256) void phase1_kernel(
    const float* __restrict__ gq, const float* __restrict__ gk,
    const float* __restrict__ gv, const float* __restrict__ gbeta)
{
    extern __shared__ float sm[];
    float* sq    = sm;
    float* sk    = sm + CC * SDK;
    float* sv    = sm + 2 * CC * SDK;
    float* sA    = sm + 3 * CC * SDK;
    float* sbeta = sA + CC * (CC + 1);
    float* sqs   = sbeta + CC;
    float* sks   = sqs + CC;

    const int t  = threadIdx.x;
    const int ch = blockIdx.x;
    const int bh = blockIdx.y;
    const size_t gbase = ((size_t)bh * LL + (size_t)ch * CC) * 128;

    {
        const float4* q4 = (const float4*)(gq + gbase);
        const float4* k4 = (const float4*)(gk + gbase);
        const float4* v4 = (const float4*)(gv + gbase);
        for (int idx = t; idx < 1024; idx += 256) {
            int r = idx >> 5, c4 = idx & 31;
            ((float4*)(sq + r * SDK))[c4] = q4[idx];
            ((float4*)(sk + r * SDK))[c4] = k4[idx];
            ((float4*)(sv + r * SDK))[c4] = v4[idx];
        }
    }
    if (t < CC) sbeta[t] = gbeta[(size_t)bh * LL + (size_t)ch * CC + t];
    __syncthreads();

    {   // row l2 norms
        int row = t >> 3, seg = t & 7;
        const float4* qr = (const float4*)(sq + row * SDK) + seg * 4;
        const float4* kr = (const float4*)(sk + row * SDK) + seg * 4;
        float s2q = 0.f, s2k = 0.f;
        #pragma unroll
        for (int i2 = 0; i2 < 4; i2++) {
            float4 a = qr[i2]; s2q += dot4(a, a);
            float4 b = kr[i2]; s2k += dot4(b, b);
        }
        #pragma unroll
        for (int off = 4; off; off >>= 1) {
            s2q += __shfl_down_sync(0xffffffffu, s2q, off, 8);
            s2k += __shfl_down_sync(0xffffffffu, s2k, off, 8);
        }
        if (seg == 0) { sqs[row] = rsqrtf(s2q + 1e-6f); sks[row] = rsqrtf(s2k + 1e-6f); }
    }
    __syncthreads();
    {
        int row = t >> 3, seg = t & 7;
        float a = sqs[row], b = sks[row];
        float4* qr = (float4*)(sq + row * SDK) + seg * 4;
        float4* kr = (float4*)(sk + row * SDK) + seg * 4;
        #pragma unroll
        for (int i2 = 0; i2 < 4; i2++) {
            float4 x = qr[i2]; x.x *= a; x.y *= a; x.z *= a; x.w *= a; qr[i2] = x;
            float4 y = kr[i2]; y.x *= b; y.y *= b; y.z *= b; y.w *= b; kr[i2] = y;
        }
    }
    __syncthreads();

    const size_t wqb   = ((size_t)(bh * NCH + ch)) * 8192;
    const size_t krb   = ((size_t)(bh * NCH + ch)) * 4096;
    const size_t abase = ((size_t)(bh * NCH + ch)) * 1024;

    {   // q-hat (k-major) -> g_wqT cols 32..63
        int d = t >> 1, half = t & 1, i0q = half * 16;
        #pragma unroll
        for (int ii = 0; ii < 16; ii += 4) {
            float4 a = make_float4(sq[(i0q + ii) * SDK + d], sq[(i0q + ii + 1) * SDK + d],
                                   sq[(i0q + ii + 2) * SDK + d], sq[(i0q + ii + 3) * SDK + d]);
            *(float4*)(g_wqT + wqb + (size_t)d * 64 + 32 + i0q + ii) = a;
        }
    }
    for (int idx = t; idx < 1024; idx += 256) {
        int r = idx >> 5, c4 = idx & 31;
        *(float4*)(g_kR + krb + (size_t)r * 128 + (c4 << 2)) =
            *(const float4*)(sk + r * SDK + (c4 << 2));
    }

    {   // dots (f32x2), stride-16 tile: rows {ti,ti+16} x cols {tj,tj+16}
        int ti = t >> 4, tj = t & 15;
        int iA = ti, iB = ti + 16;
        int jA = tj, jB = tj + 16;
        ull pkkAA = 0, pkkAB = 0, pkkBA = 0, pkkBB = 0;
        ull pqkAA = 0, pqkAB = 0, pqkBA = 0, pqkBB = 0;
        const ulonglong2* kiA = (const ulonglong2*)(sk + iA * SDK);
        const ulonglong2* kiB = (const ulonglong2*)(sk + iB * SDK);
        const ulonglong2* kjA = (const ulonglong2*)(sk + jA * SDK);
        const ulonglong2* kjB = (const ulonglong2*)(sk + jB * SDK);
        const ulonglong2* qiA = (const ulonglong2*)(sq + iA * SDK);
        const ulonglong2* qiB = (const ulonglong2*)(sq + iB * SDK);
        #pragma unroll 8
        for (int d4 = 0; d4 < 32; d4++) {
            ulonglong2 A0 = kiA[d4], A1 = kiB[d4];
            ulonglong2 B0 = kjA[d4], B1 = kjB[d4];
            ulonglong2 C0 = qiA[d4], C1 = qiB[d4];
            fm2(pkkAA, A0.x, B0.x); fm2(pkkAA, A0.y, B0.y);
            fm2(pkkAB, A0.x, B1.x); fm2(pkkAB, A0.y, B1.y);
            fm2(pkkBA, A1.x, B0.x); fm2(pkkBA, A1.y, B0.y);
            fm2(pkkBB, A1.x, B1.x); fm2(pkkBB, A1.y, B1.y);
            fm2(pqkAA, C0.x, B0.x); fm2(pqkAA, C0.y, B0.y);
            fm2(pqkAB, C0.x, B1.x); fm2(pqkAB, C0.y, B1.y);
            fm2(pqkBA, C1.x, B0.x); fm2(pqkBA, C1.y, B0.y);
            fm2(pqkBB, C1.x, B1.x); fm2(pqkBB, C1.y, B1.y);
        }
        float2 e;
        e = upk(pkkAA); float dkkAA = e.x + e.y;
        e = upk(pkkAB); float dkkAB = e.x + e.y;
        e = upk(pkkBA); float dkkBA = e.x + e.y;
        e = upk(pkkBB); float dkkBB = e.x + e.y;
        e = upk(pqkAA); float dqkAA = e.x + e.y;
        e = upk(pqkAB); float dqkAB = e.x + e.y;
        e = upk(pqkBA); float dqkBA = e.x + e.y;
        e = upk(pqkBB); float dqkBB = e.x + e.y;
        float biA = sbeta[iA], biB = sbeta[iB];
        sA[iA * 33 + jA] = (iA > jA) ? -biA * dkkAA : 0.f;
        sA[iA * 33 + jB] = (iA > jB) ? -biA * dkkAB : 0.f;
        sA[iB * 33 + jA] = (iB > jA) ? -biB * dkkBA : 0.f;
        sA[iB * 33 + jB] = (iB > jB) ? -biB * dkkBB : 0.f;
        #define ATW(ii, jj, val) g_at2[abase + (size_t)(ii) * 32 + \
            (size_t)(((((jj) >> 2) ^ ((ii) & 7)) << 2) + ((jj) & 3))] = (val)
        ATW(iA, jA, (iA >= jA) ? dqkAA : 0.f);
        ATW(iA, jB, (iA >= jB) ? dqkAB : 0.f);
        ATW(iB, jA, (iB >= jA) ? dqkBA : 0.f);
        ATW(iB, jB, (iB >= jB) ? dqkBB : 0.f);
        #undef ATW
    }
    __syncthreads();

    // forward substitution (exact reference order), warp 0
    if (t < 32) {
        int lane = t;
        for (int i = 1; i < CC; i++) {
            float s = 0.f;
            if (lane < i) {
                for (int kk = lane + 1; kk < i; kk++)
                    s += sA[i * 33 + kk] * sA[kk * 33 + lane];
            }
            __syncwarp();
            if (lane < i) sA[i * 33 + lane] += s;
            __syncwarp();
        }
        sA[lane * 33 + lane] = 1.0f;
    }
    __syncthreads();

    for (int idx = t; idx < 1024; idx += 256) {
        int i = idx >> 5, j = idx & 31;
        sA[i * 33 + j] *= sbeta[j];
    }
    __syncthreads();

    // u = Abeta @ v ; w = Abeta @ k-hat
    // Each thread: rows i0,i0+1 x cols {cA..cA+3} and {cB..cB+3} (16B lane stride).
    {
        int p = t >> 4, dseg = t & 15;
        int i0 = 2 * p;
        int cA = dseg << 2;
        int cB = 64 + (dseg << 2);
        ulonglong2 u0a = {0,0}, u0b = {0,0}, u1a = {0,0}, u1b = {0,0};
        ulonglong2 w0a = {0,0}, w0b = {0,0}, w1a = {0,0}, w1b = {0,0};
        #pragma unroll 4
        for (int j = 0; j < CC; j++) {
            ull A0 = pk1(sA[i0 * 33 + j]);
            ull A1 = pk1(sA[(i0 + 1) * 33 + j]);
            ulonglong2 va = *(const ulonglong2*)(sv + j * SDK + cA);
            ulonglong2 vb = *(const ulonglong2*)(sv + j * SDK + cB);
            ulonglong2 ka = *(const ulonglong2*)(sk + j * SDK + cA);
            ulonglong2 kb = *(const ulonglong2*)(sk + j * SDK + cB);
            fm2(u0a.x, A0, va.x); fm2(u0a.y, A0, va.y);
            fm2(u0b.x, A0, vb.x); fm2(u0b.y, A0, vb.y);
            fm2(u1a.x, A1, va.x); fm2(u1a.y, A1, va.y);
            fm2(u1b.x, A1, vb.x); fm2(u1b.y, A1, vb.y);
            fm2(w0a.x, A0, ka.x); fm2(w0a.y, A0, ka.y);
            fm2(w0b.x, A0, kb.x); fm2(w0b.y, A0, kb.y);
            fm2(w1a.x, A1, ka.x); fm2(w1a.y, A1, ka.y);
            fm2(w1b.x, A1, kb.x); fm2(w1b.y, A1, kb.y);
        }
        int slA = dseg >> 2, offA = (dseg & 3) << 2;
        size_t ubA = (((size_t)(bh * 8 + slA)) * NCH + ch) * 512;
        size_t ubB = (((size_t)(bh * 8 + 4 + slA)) * NCH + ch) * 512;
        *(ulonglong2*)(g_u2 + ubA + (size_t)i0 * 16 + offA)       = u0a;
        *(ulonglong2*)(g_u2 + ubB + (size_t)i0 * 16 + offA)       = u0b;
        *(ulonglong2*)(g_u2 + ubA + (size_t)(i0 + 1) * 16 + offA) = u1a;
        *(ulonglong2*)(g_u2 + ubB + (size_t)(i0 + 1) * 16 + offA) = u1b;
        float wA0[4], wB0[4], wA1[4], wB1[4];
        float2 e;
        e = upk(w0a.x); wA0[0] = e.x; wA0[1] = e.y;
        e = upk(w0a.y); wA0[2] = e.x; wA0[3] = e.y;
        e = upk(w0b.x); wB0[0] = e.x; wB0[1] = e.y;
        e = upk(w0b.y); wB0[2] = e.x; wB0[3] = e.y;
        e = upk(w1a.x); wA1[0] = e.x; wA1[1] = e.y;
        e = upk(w1a.y); wA1[2] = e.x; wA1[3] = e.y;
        e = upk(w1b.x); wB1[0] = e.x; wB1[1] = e.y;
        e = upk(w1b.y); wB1[2] = e.x; wB1[3] = e.y;
        #pragma unroll
        for (int dd = 0; dd < 4; dd++) {
            *(float2*)(g_wqT + wqb + (size_t)(cA + dd) * 64 + i0) =
                make_float2(wA0[dd], wA1[dd]);
            *(float2*)(g_wqT + wqb + (size_t)(cB + dd) * 64 + i0) =
                make_float2(wB0[dd], wB1[dd]);
        }
    }
}

// =====================================================================
// Phase 2: sequential scan, dv split 8x16. grid (8, BHT), 256 threads.
// =====================================================================
#define BUF_F   13824
#define OFF_K   8192
#define OFF_AT  12288
#define OFF_U   13312
#define TX_BYTES 55296u

__global__ __launch_bounds__(256) void phase2_kernel(
    float* __restrict__ out, float* __restrict__ Sout)
{
    extern __shared__ float sm[];
    float* sS   = sm + 4;
    float* po   = sm + 4 + 2048;
    float* bufs = sm + 4 + 2048 + 512;

    const int t = threadIdx.x;
    const int slice = blockIdx.x;
    const int bh    = blockIdx.y;
    const int c0    = slice * 16;

    const int lane = t & 31, warp = t >> 5;
    const int tl = lane & 7, kg = lane >> 3;
    const int tile = warp * 8 + tl;
    const int tr = tile & 15, tc = tile >> 4;
    const int i0 = tr << 2;
    const int cb4 = tc << 2;

    const uint32_t mb0 = s2u(sm), mb1 = mb0 + 8;

    for (int idx = t; idx < 2048; idx += 256) sS[idx] = 0.f;
    if (t == 0) { mbar_init(mb0, 1); mbar_init(mb1, 1); }
    __syncthreads();

    const size_t cb0 = (size_t)bh * NCH;
    const size_t ublk = ((size_t)(bh * 8 + slice)) * NCH;
    if (t == 0) {
        mbar_expect(mb0, TX_BYTES);
        bulkcp(s2u(bufs),           g_wqT + cb0 * 8192, 32768, mb0);
        bulkcp(s2u(bufs + OFF_K),   g_kR  + cb0 * 4096, 16384, mb0);
        bulkcp(s2u(bufs + OFF_AT),  g_at2 + cb0 * 1024, 4096, mb0);
        bulkcp(s2u(bufs + OFF_U),   g_u2  + ublk * 512, 2048, mb0);
    }

    for (int ch = 0; ch < NCH; ch++) {
        const int b = ch & 1;
        float* B  = bufs + b * BUF_F;
        float* bu = B + OFF_U;

        __syncthreads();
        if (t == 0 && ch + 1 < NCH) {
            uint32_t mb = b ? mb0 : mb1;
            float* B2 = bufs + (b ^ 1) * BUF_F;
            const size_t cb = cb0 + ch + 1;
            mbar_expect(mb, TX_BYTES);
            bulkcp(s2u(B2),          g_wqT + cb * 8192, 32768, mb);
            bulkcp(s2u(B2 + OFF_K),  g_kR  + cb * 4096, 16384, mb);
            bulkcp(s2u(B2 + OFF_AT), g_at2 + cb * 1024, 4096, mb);
            bulkcp(s2u(B2 + OFF_U),  g_u2  + (ublk + ch + 1) * 512, 2048, mb);
        }
        mbar_wait(b ? mb1 : mb0, (ch >> 1) & 1);

        // ---- P = [w;q]@S : 4x4 tile, k-split-4 ----
        ull a00 = 0, a01 = 0, a10 = 0, a11 = 0, a20 = 0, a21 = 0, a30 = 0, a31 = 0;
        {
            const float* wp = B + (kg << 5) * 64 + i0;
            const float* sbase = sS + (kg << 5) * 16;
            #pragma unroll
            for (int k = 0; k < 32; k++) {
                float4 w4 = *(const float4*)(wp + k * 64);
                const int phys = ((tc ^ ((k >> 2) & 3) ^ kg) << 2);
                ulonglong2 s2 = *(const ulonglong2*)(sbase + k * 16 + phys);
                fm2(a00, pk1(w4.x), s2.x); fm2(a01, pk1(w4.x), s2.y);
                fm2(a10, pk1(w4.y), s2.x); fm2(a11, pk1(w4.y), s2.y);
                fm2(a20, pk1(w4.z), s2.x); fm2(a21, pk1(w4.z), s2.y);
                fm2(a30, pk1(w4.w), s2.x); fm2(a31, pk1(w4.w), s2.y);
            }
        }
        #pragma unroll
        for (int m = 8; m <= 16; m <<= 1) {
            a00 = ad2r(a00, __shfl_xor_sync(0xffffffffu, a00, m));
            a01 = ad2r(a01, __shfl_xor_sync(0xffffffffu, a01, m));
            a10 = ad2r(a10, __shfl_xor_sync(0xffffffffu, a10, m));
            a11 = ad2r(a11, __shfl_xor_sync(0xffffffffu, a11, m));
            a20 = ad2r(a20, __shfl_xor_sync(0xffffffffu, a20, m));
            a21 = ad2r(a21, __shfl_xor_sync(0xffffffffu, a21, m));
            a30 = ad2r(a30, __shfl_xor_sync(0xffffffffu, a30, m));
            a31 = ad2r(a31, __shfl_xor_sync(0xffffffffu, a31, m));
        }
        {   // distributed tail: lane kg handles row i0+kg
            ull ax, ay;
            if (kg == 0)      { ax = a00; ay = a01; }
            else if (kg == 1) { ax = a10; ay = a11; }
            else if (kg == 2) { ax = a20; ay = a21; }
            else              { ax = a30; ay = a31; }
            float2 lo = upk(ax), hi = upk(ay);
            const int row = i0 + kg;
            if (tr < 8) {
                float* up = bu + row * 16 + cb4;
                float4 u0 = *(const float4*)up;
                u0.x -= lo.x; u0.y -= lo.y; u0.z -= hi.x; u0.w -= hi.y;
                *(float4*)up = u0;
            } else {
                *(float4*)(po + (row - 32) * 16 + cb4) =
                    make_float4(lo.x, lo.y, hi.x, hi.y);
            }
        }
        __syncthreads();

        if (t < 128) {
            const int rt = t >> 2, ct = t & 3;
            const int rb = rt << 2;
            const int physc = ((ct ^ ((rt ^ (rt >> 3)) & 3)) << 2);
            float* sp0 = sS + rb * 16 + physc;
            ulonglong2 s0 = *(const ulonglong2*)(sp0);
            ulonglong2 s1 = *(const ulonglong2*)(sp0 + 16);
            ulonglong2 s2v = *(const ulonglong2*)(sp0 + 32);
            ulonglong2 s3 = *(const ulonglong2*)(sp0 + 48);
            const float* kp = B + OFF_K + rb;
            const float* up2 = bu + (ct << 2);
            #pragma unroll 8
            for (int j = 0; j < 32; j++) {
                float4 k4 = *(const float4*)kp;
                ulonglong2 u2 = *(const ulonglong2*)up2;
                fm2(s0.x,  pk1(k4.x), u2.x); fm2(s0.y,  pk1(k4.x), u2.y);
                fm2(s1.x,  pk1(k4.y), u2.x); fm2(s1.y,  pk1(k4.y), u2.y);
                fm2(s2v.x, pk1(k4.z), u2.x); fm2(s2v.y, pk1(k4.z), u2.y);
                fm2(s3.x,  pk1(k4.w), u2.x); fm2(s3.y,  pk1(k4.w), u2.y);
                kp += 128; up2 += 16;
            }
            *(ulonglong2*)(sp0)      = s0;
            *(ulonglong2*)(sp0 + 16) = s1;
            *(ulonglong2*)(sp0 + 32) = s2v;
            *(ulonglong2*)(sp0 + 48) = s3;
        } else {
            const int ii2 = (t - 128) >> 2, cq = t & 3;
            const int asw = ii2 & 7;
            ulonglong2 acc = *(const ulonglong2*)(po + ii2 * 16 + (cq << 2));
            const float* atr = B + OFF_AT + ii2 * 32;
            const float* Up = bu + (cq << 2);
            #pragma unroll
            for (int j4 = 0; j4 < 8; j4++) {
                float4 a4 = *(const float4*)(atr + ((j4 ^ asw) << 2));
                const float* u0p = Up + (j4 << 6);
                ulonglong2 U0 = *(const ulonglong2*)(u0p);
                ulonglong2 U1 = *(const ulonglong2*)(u0p + 16);
                ulonglong2 U2 = *(const ulonglong2*)(u0p + 32);
                ulonglong2 U3 = *(const ulonglong2*)(u0p + 48);
                fm2(acc.x, pk1(a4.x), U0.x); fm2(acc.y, pk1(a4.x), U0.y);
                fm2(acc.x, pk1(a4.y), U1.x); fm2(acc.y, pk1(a4.y), U1.y);
                fm2(acc.x, pk1(a4.z), U2.x); fm2(acc.y, pk1(a4.z), U2.y);
                fm2(acc.x, pk1(a4.w), U3.x); fm2(acc.y, pk1(a4.w), U3.y);
            }
            float2 f0 = upk(acc.x), f1 = upk(acc.y);
            size_t off = ((size_t)bh * LL + (size_t)ch * CC + ii2) * 128 + c0 + (cq << 2);
            *(float4*)(out + off) = make_float4(f0.x, f0.y, f1.x, f1.y);
        }
    }

    if (Sout != nullptr) {
        __syncthreads();
        size_t sb = (size_t)bh * 128 * 128;
        for (int idx = t; idx < 2048; idx += 256) {
            int r = idx >> 4, c = idx & 15;
            int phys = ((((c >> 2) ^ ((r >> 2) & 3) ^ ((r >> 5) & 3)) & 3) << 2) + (c & 3);
            Sout[sb + (size_t)r * 128 + c0 + c] = sS[r * 16 + phys];
        }
    }
}

// =====================================================================
#define P1_SMEM ((3 * CC * SDK + CC * (CC + 1) + 3 * CC) * (int)sizeof(float))
#define P2_SMEM ((4 + 2048 + 512 + 2 * BUF_F) * (int)sizeof(float))

extern "C" void kernel_launch(void* const* d_in, const int* in_sizes, int n_in,
                              void* d_out, int out_size)
{
    const float* q    = (const float*)d_in[0];
    const float* k    = (const float*)d_in[1];
    const float* v    = (const float*)d_in[2];
    const float* beta = (const float*)d_in[3];
    float* out = (float*)d_out;
    float* Sout = ((size_t)out_size >= OUT_ELEMS + S_ELEMS) ? (out + OUT_ELEMS) : nullptr;

    cudaFuncSetAttribute(phase1_kernel, cudaFuncAttributeMaxDynamicSharedMemorySize, P1_SMEM);
    cudaFuncSetAttribute(phase2_kernel, cudaFuncAttributeMaxDynamicSharedMemorySize, P2_SMEM);

    phase1_kernel<<<dim3(NCH, BHT), 256, P1_SMEM>>>(q, k, v, beta);
    phase2_kernel<<<dim3(8, BHT), 256, P2_SMEM>>>(out, Sout);
}

// round 17
// speedup vs baseline: 1.7414x; 1.0675x over previous
#include <cuda_runtime.h>
#include <cuda_bf16.h>
#include <cstdint>
#include <cstddef>

#define LL   4096
#define CC   32
#define NCH  128
#define BHT  16
#define SDK  132
#define OUT_ELEMS  ((size_t)BHT * LL * 128)
#define S_ELEMS    ((size_t)BHT * 128 * 128)

typedef unsigned long long ull;

// g_wqT: [bh][ch][128][64] k-major: cols 0..31 = w rows, 32..63 = q-hat rows
// g_kR : [bh][ch][32][128] k-hat row-major
// g_at2: [bh][ch][32][32]  masked attn, chunks swizzled (j4 ^ (i&7))
// g_u2 : [bh][slice8][ch][32][16]
__device__ float g_wqT[(size_t)BHT * NCH * 128 * 64];
__device__ float g_kR [(size_t)BHT * NCH * 32 * 128];
__device__ float g_at2[(size_t)BHT * NCH * 32 * 32];
__device__ float g_u2 [(size_t)BHT * 8 * NCH * 32 * 16];

__device__ __forceinline__ float dot4(float4 a, float4 b) {
    return a.x * b.x + a.y * b.y + a.z * b.z + a.w * b.w;
}
__device__ __forceinline__ ull pk1(float x) {
    ull r; asm("mov.b64 %0,{%1,%1};" : "=l"(r) : "f"(x)); return r;
}
__device__ __forceinline__ void fm2(ull& a, ull b, ull c) {
    asm("fma.rn.f32x2 %0,%1,%2,%3;" : "=l"(a) : "l"(b), "l"(c), "l"(a));
}
__device__ __forceinline__ ull ad2r(ull a, ull b) {
    ull r; asm("add.rn.f32x2 %0,%1,%2;" : "=l"(r) : "l"(a), "l"(b)); return r;
}
__device__ __forceinline__ float2 upk(ull a) {
    float2 f; asm("mov.b64 {%0,%1},%2;" : "=f"(f.x), "=f"(f.y) : "l"(a)); return f;
}
__device__ __forceinline__ uint32_t s2u(const void* p) {
    return (uint32_t)__cvta_generic_to_shared(p);
}
__device__ __forceinline__ void mbar_init(uint32_t m, uint32_t c) {
    asm volatile("mbarrier.init.shared.b64 [%0], %1;" :: "r"(m), "r"(c) : "memory");
}
__device__ __forceinline__ void mbar_expect(uint32_t m, uint32_t b) {
    asm volatile("mbarrier.arrive.expect_tx.shared.b64 _, [%0], %1;" :: "r"(m), "r"(b) : "memory");
}
__device__ __forceinline__ void mbar_wait(uint32_t m, uint32_t p) {
    asm volatile(
        "{\n\t.reg .pred P;\n\tW%=:\n\t"
        "mbarrier.try_wait.parity.acquire.cta.shared::cta.b64 P, [%0], %1, 0x989680;\n\t"
        "@P bra D%=;\n\tbra W%=;\n\tD%=:\n\t}" :: "r"(m), "r"(p) : "memory");
}
__device__ __forceinline__ void bulkcp(uint32_t d, const void* s, uint32_t b, uint32_t m) {
    asm volatile("cp.async.bulk.shared::cta.global.mbarrier::complete_tx::bytes [%0], [%1], %2, [%3];"
        :: "r"(d), "l"(s), "r"(b), "r"(m) : "memory");
}

// =====================================================================
// Phase 1: grid (NCH, BHT), 256 threads. Norm scales folded (no
// normalize pass); shuffle-broadcast forward substitution.
// =====================================================================
__global__ __launch_bounds__(256) void phase1_kernel(
    const float* __restrict__ gq, const float* __restrict__ gk,
    const float* __restrict__ gv, const float* __restrict__ gbeta)
{
    extern __shared__ float sm[];
    float* sq    = sm;
    float* sk    = sm + CC * SDK;
    float* sv    = sm + 2 * CC * SDK;
    float* sA    = sm + 3 * CC * SDK;
    float* sbeta = sA + CC * (CC + 1);
    float* sqs   = sbeta + CC;
    float* sks   = sqs + CC;

    const int t  = threadIdx.x;
    const int ch = blockIdx.x;
    const int bh = blockIdx.y;
    const size_t gbase = ((size_t)bh * LL + (size_t)ch * CC) * 128;

    {
        const float4* q4 = (const float4*)(gq + gbase);
        const float4* k4 = (const float4*)(gk + gbase);
        const float4* v4 = (const float4*)(gv + gbase);
        for (int idx = t; idx < 1024; idx += 256) {
            int r = idx >> 5, c4 = idx & 31;
            ((float4*)(sq + r * SDK))[c4] = q4[idx];
            ((float4*)(sk + r * SDK))[c4] = k4[idx];
            ((float4*)(sv + r * SDK))[c4] = v4[idx];
        }
    }
    if (t < CC) sbeta[t] = gbeta[(size_t)bh * LL + (size_t)ch * CC + t];
    __syncthreads();

    {   // row l2 norms -> sqs/sks only (no normalize pass)
        int row = t >> 3, seg = t & 7;
        const float4* qr = (const float4*)(sq + row * SDK) + seg * 4;
        const float4* kr = (const float4*)(sk + row * SDK) + seg * 4;
        float s2q = 0.f, s2k = 0.f;
        #pragma unroll
        for (int i2 = 0; i2 < 4; i2++) {
            float4 a = qr[i2]; s2q += dot4(a, a);
            float4 b = kr[i2]; s2k += dot4(b, b);
        }
        #pragma unroll
        for (int off = 4; off; off >>= 1) {
            s2q += __shfl_down_sync(0xffffffffu, s2q, off, 8);
            s2k += __shfl_down_sync(0xffffffffu, s2k, off, 8);
        }
        if (seg == 0) { sqs[row] = rsqrtf(s2q + 1e-6f); sks[row] = rsqrtf(s2k + 1e-6f); }
    }
    __syncthreads();

    const size_t wqb   = ((size_t)(bh * NCH + ch)) * 8192;
    const size_t krb   = ((size_t)(bh * NCH + ch)) * 4096;
    const size_t abase = ((size_t)(bh * NCH + ch)) * 1024;

    {   // q-hat (k-major, scale folded) -> g_wqT cols 32..63
        int d = t >> 1, half = t & 1, i0q = half * 16;
        #pragma unroll
        for (int ii = 0; ii < 16; ii += 4) {
            int r0 = i0q + ii;
            float4 a = make_float4(sq[r0 * SDK + d] * sqs[r0],
                                   sq[(r0 + 1) * SDK + d] * sqs[r0 + 1],
                                   sq[(r0 + 2) * SDK + d] * sqs[r0 + 2],
                                   sq[(r0 + 3) * SDK + d] * sqs[r0 + 3]);
            *(float4*)(g_wqT + wqb + (size_t)d * 64 + 32 + r0) = a;
        }
    }
    for (int idx = t; idx < 1024; idx += 256) {
        int r = idx >> 5, c4 = idx & 31;
        float s = sks[r];
        float4 kv = *(const float4*)(sk + r * SDK + (c4 << 2));
        kv.x *= s; kv.y *= s; kv.z *= s; kv.w *= s;
        *(float4*)(g_kR + krb + (size_t)r * 128 + (c4 << 2)) = kv;
    }

    {   // dots (f32x2) on raw q/k, stride-16 tile; scales applied at store
        int ti = t >> 4, tj = t & 15;
        int iA = ti, iB = ti + 16;
        int jA = tj, jB = tj + 16;
        ull pkkAA = 0, pkkAB = 0, pkkBA = 0, pkkBB = 0;
        ull pqkAA = 0, pqkAB = 0, pqkBA = 0, pqkBB = 0;
        const ulonglong2* kiA = (const ulonglong2*)(sk + iA * SDK);
        const ulonglong2* kiB = (const ulonglong2*)(sk + iB * SDK);
        const ulonglong2* kjA = (const ulonglong2*)(sk + jA * SDK);
        const ulonglong2* kjB = (const ulonglong2*)(sk + jB * SDK);
        const ulonglong2* qiA = (const ulonglong2*)(sq + iA * SDK);
        const ulonglong2* qiB = (const ulonglong2*)(sq + iB * SDK);
        #pragma unroll 8
        for (int d4 = 0; d4 < 32; d4++) {
            ulonglong2 A0 = kiA[d4], A1 = kiB[d4];
            ulonglong2 B0 = kjA[d4], B1 = kjB[d4];
            ulonglong2 C0 = qiA[d4], C1 = qiB[d4];
            fm2(pkkAA, A0.x, B0.x); fm2(pkkAA, A0.y, B0.y);
            fm2(pkkAB, A0.x, B1.x); fm2(pkkAB, A0.y, B1.y);
            fm2(pkkBA, A1.x, B0.x); fm2(pkkBA, A1.y, B0.y);
            fm2(pkkBB, A1.x, B1.x); fm2(pkkBB, A1.y, B1.y);
            fm2(pqkAA, C0.x, B0.x); fm2(pqkAA, C0.y, B0.y);
            fm2(pqkAB, C0.x, B1.x); fm2(pqkAB, C0.y, B1.y);
            fm2(pqkBA, C1.x, B0.x); fm2(pqkBA, C1.y, B0.y);
            fm2(pqkBB, C1.x, B1.x); fm2(pqkBB, C1.y, B1.y);
        }
        float2 e;
        e = upk(pkkAA); float dkkAA = e.x + e.y;
        e = upk(pkkAB); float dkkAB = e.x + e.y;
        e = upk(pkkBA); float dkkBA = e.x + e.y;
        e = upk(pkkBB); float dkkBB = e.x + e.y;
        e = upk(pqkAA); float dqkAA = e.x + e.y;
        e = upk(pqkAB); float dqkAB = e.x + e.y;
        e = upk(pqkBA); float dqkBA = e.x + e.y;
        e = upk(pqkBB); float dqkBB = e.x + e.y;
        float kiAs = sks[iA], kiBs = sks[iB];
        float kjAs = sks[jA], kjBs = sks[jB];
        float qiAs = sqs[iA], qiBs = sqs[iB];
        float cA_ = -sbeta[iA] * kiAs, cB_ = -sbeta[iB] * kiBs;
        sA[iA * 33 + jA] = (iA > jA) ? cA_ * kjAs * dkkAA : 0.f;
        sA[iA * 33 + jB] = (iA > jB) ? cA_ * kjBs * dkkAB : 0.f;
        sA[iB * 33 + jA] = (iB > jA) ? cB_ * kjAs * dkkBA : 0.f;
        sA[iB * 33 + jB] = (iB > jB) ? cB_ * kjBs * dkkBB : 0.f;
        #define ATW(ii, jj, val) g_at2[abase + (size_t)(ii) * 32 + \
            (size_t)(((((jj) >> 2) ^ ((ii) & 7)) << 2) + ((jj) & 3))] = (val)
        ATW(iA, jA, (iA >= jA) ? qiAs * kjAs * dqkAA : 0.f);
        ATW(iA, jB, (iA >= jB) ? qiAs * kjBs * dqkAB : 0.f);
        ATW(iB, jA, (iB >= jA) ? qiBs * kjAs * dqkBA : 0.f);
        ATW(iB, jB, (iB >= jB) ? qiBs * kjBs * dqkBB : 0.f);
        #undef ATW
    }
    __syncthreads();

    // forward substitution: shuffle-broadcast (leading zero terms are exact)
    if (t < 32) {
        const int lane = t;
        for (int i = 1; i < CC; i++) {
            float a = sA[i * 33 + lane];
            float f = a;
            for (int k = 1; k < i; k++) {
                float bk = __shfl_sync(0xffffffffu, a, k);
                f += bk * sA[k * 33 + lane];
            }
            __syncwarp();
            if (lane < i) sA[i * 33 + lane] = f;
            __syncwarp();
        }
        sA[lane * 33 + lane] = 1.0f;
    }
    __syncthreads();

    for (int idx = t; idx < 1024; idx += 256) {
        int i = idx >> 5, j = idx & 31;
        sA[i * 33 + j] *= sbeta[j];
    }
    __syncthreads();

    // u = Abeta @ v ; w = (Abeta*ks_j) @ k_raw  (k-hat scale folded on the fly)
    {
        int p = t >> 4, dseg = t & 15;
        int i0 = 2 * p;
        int cA = dseg << 2;
        int cB = 64 + (dseg << 2);
        ulonglong2 u0a = {0,0}, u0b = {0,0}, u1a = {0,0}, u1b = {0,0};
        ulonglong2 w0a = {0,0}, w0b = {0,0}, w1a = {0,0}, w1b = {0,0};
        #pragma unroll 4
        for (int j = 0; j < CC; j++) {
            float av0 = sA[i0 * 33 + j];
            float av1 = sA[(i0 + 1) * 33 + j];
            float sksj = sks[j];
            ull A0 = pk1(av0);
            ull A1 = pk1(av1);
            ull W0 = pk1(av0 * sksj);
            ull W1 = pk1(av1 * sksj);
            ulonglong2 va = *(const ulonglong2*)(sv + j * SDK + cA);
            ulonglong2 vb = *(const ulonglong2*)(sv + j * SDK + cB);
            ulonglong2 ka = *(const ulonglong2*)(sk + j * SDK + cA);
            ulonglong2 kb = *(const ulonglong2*)(sk + j * SDK + cB);
            fm2(u0a.x, A0, va.x); fm2(u0a.y, A0, va.y);
            fm2(u0b.x, A0, vb.x); fm2(u0b.y, A0, vb.y);
            fm2(u1a.x, A1, va.x); fm2(u1a.y, A1, va.y);
            fm2(u1b.x, A1, vb.x); fm2(u1b.y, A1, vb.y);
            fm2(w0a.x, W0, ka.x); fm2(w0a.y, W0, ka.y);
            fm2(w0b.x, W0, kb.x); fm2(w0b.y, W0, kb.y);
            fm2(w1a.x, W1, ka.x); fm2(w1a.y, W1, ka.y);
            fm2(w1b.x, W1, kb.x); fm2(w1b.y, W1, kb.y);
        }
        int slA = dseg >> 2, offA = (dseg & 3) << 2;
        size_t ubA = (((size_t)(bh * 8 + slA)) * NCH + ch) * 512;
        size_t ubB = (((size_t)(bh * 8 + 4 + slA)) * NCH + ch) * 512;
        *(ulonglong2*)(g_u2 + ubA + (size_t)i0 * 16 + offA)       = u0a;
        *(ulonglong2*)(g_u2 + ubB + (size_t)i0 * 16 + offA)       = u0b;
        *(ulonglong2*)(g_u2 + ubA + (size_t)(i0 + 1) * 16 + offA) = u1a;
        *(ulonglong2*)(g_u2 + ubB + (size_t)(i0 + 1) * 16 + offA) = u1b;
        float wA0[4], wB0[4], wA1[4], wB1[4];
        float2 e;
        e = upk(w0a.x); wA0[0] = e.x; wA0[1] = e.y;
        e = upk(w0a.y); wA0[2] = e.x; wA0[3] = e.y;
        e = upk(w0b.x); wB0[0] = e.x; wB0[1] = e.y;
        e = upk(w0b.y); wB0[2] = e.x; wB0[3] = e.y;
        e = upk(w1a.x); wA1[0] = e.x; wA1[1] = e.y;
        e = upk(w1a.y); wA1[2] = e.x; wA1[3] = e.y;
        e = upk(w1b.x); wB1[0] = e.x; wB1[1] = e.y;
        e = upk(w1b.y); wB1[2] = e.x; wB1[3] = e.y;
        #pragma unroll
        for (int dd = 0; dd < 4; dd++) {
            *(float2*)(g_wqT + wqb + (size_t)(cA + dd) * 64 + i0) =
                make_float2(wA0[dd], wA1[dd]);
            *(float2*)(g_wqT + wqb + (size_t)(cB + dd) * 64 + i0) =
                make_float2(wB0[dd], wB1[dd]);
        }
    }
}

// =====================================================================
// Phase 2 (unchanged): sequential scan, dv split 8x16. grid (8, BHT).
// =====================================================================
#define BUF_F   13824
#define OFF_K   8192
#define OFF_AT  12288
#define OFF_U   13312
#define TX_BYTES 55296u

__global__ __launch_bounds__(256) void phase2_kernel(
    float* __restrict__ out, float* __restrict__ Sout)
{
    extern __shared__ float sm[];
    float* sS   = sm + 4;
    float* po   = sm + 4 + 2048;
    float* bufs = sm + 4 + 2048 + 512;

    const int t = threadIdx.x;
    const int slice = blockIdx.x;
    const int bh    = blockIdx.y;
    const int c0    = slice * 16;

    const int lane = t & 31, warp = t >> 5;
    const int tl = lane & 7, kg = lane >> 3;
    const int tile = warp * 8 + tl;
    const int tr = tile & 15, tc = tile >> 4;
    const int i0 = tr << 2;
    const int cb4 = tc << 2;

    const uint32_t mb0 = s2u(sm), mb1 = mb0 + 8;

    for (int idx = t; idx < 2048; idx += 256) sS[idx] = 0.f;
    if (t == 0) { mbar_init(mb0, 1); mbar_init(mb1, 1); }
    __syncthreads();

    const size_t cb0 = (size_t)bh * NCH;
    const size_t ublk = ((size_t)(bh * 8 + slice)) * NCH;
    if (t == 0) {
        mbar_expect(mb0, TX_BYTES);
        bulkcp(s2u(bufs),           g_wqT + cb0 * 8192, 32768, mb0);
        bulkcp(s2u(bufs + OFF_K),   g_kR  + cb0 * 4096, 16384, mb0);
        bulkcp(s2u(bufs + OFF_AT),  g_at2 + cb0 * 1024, 4096, mb0);
        bulkcp(s2u(bufs + OFF_U),   g_u2  + ublk * 512, 2048, mb0);
    }

    for (int ch = 0; ch < NCH; ch++) {
        const int b = ch & 1;
        float* B  = bufs + b * BUF_F;
        float* bu = B + OFF_U;

        __syncthreads();
        if (t == 0 && ch + 1 < NCH) {
            uint32_t mb = b ? mb0 : mb1;
            float* B2 = bufs + (b ^ 1) * BUF_F;
            const size_t cb = cb0 + ch + 1;
            mbar_expect(mb, TX_BYTES);
            bulkcp(s2u(B2),          g_wqT + cb * 8192, 32768, mb);
            bulkcp(s2u(B2 + OFF_K),  g_kR  + cb * 4096, 16384, mb);
            bulkcp(s2u(B2 + OFF_AT), g_at2 + cb * 1024, 4096, mb);
            bulkcp(s2u(B2 + OFF_U),  g_u2  + (ublk + ch + 1) * 512, 2048, mb);
        }
        mbar_wait(b ? mb1 : mb0, (ch >> 1) & 1);

        // ---- P = [w;q]@S : 4x4 tile, k-split-4 ----
        ull a00 = 0, a01 = 0, a10 = 0, a11 = 0, a20 = 0, a21 = 0, a30 = 0, a31 = 0;
        {
            const float* wp = B + (kg << 5) * 64 + i0;
            const float* sbase = sS + (kg << 5) * 16;
            #pragma unroll
            for (int k = 0; k < 32; k++) {
                float4 w4 = *(const float4*)(wp + k * 64);
                const int phys = ((tc ^ ((k >> 2) & 3) ^ kg) << 2);
                ulonglong2 s2 = *(const ulonglong2*)(sbase + k * 16 + phys);
                fm2(a00, pk1(w4.x), s2.x); fm2(a01, pk1(w4.x), s2.y);
                fm2(a10, pk1(w4.y), s2.x); fm2(a11, pk1(w4.y), s2.y);
                fm2(a20, pk1(w4.z), s2.x); fm2(a21, pk1(w4.z), s2.y);
                fm2(a30, pk1(w4.w), s2.x); fm2(a31, pk1(w4.w), s2.y);
            }
        }
        #pragma unroll
        for (int m = 8; m <= 16; m <<= 1) {
            a00 = ad2r(a00, __shfl_xor_sync(0xffffffffu, a00, m));
            a01 = ad2r(a01, __shfl_xor_sync(0xffffffffu, a01, m));
            a10 = ad2r(a10, __shfl_xor_sync(0xffffffffu, a10, m));
            a11 = ad2r(a11, __shfl_xor_sync(0xffffffffu, a11, m));
            a20 = ad2r(a20, __shfl_xor_sync(0xffffffffu, a20, m));
            a21 = ad2r(a21, __shfl_xor_sync(0xffffffffu, a21, m));
            a30 = ad2r(a30, __shfl_xor_sync(0xffffffffu, a30, m));
            a31 = ad2r(a31, __shfl_xor_sync(0xffffffffu, a31, m));
        }
        {   // distributed tail: lane kg handles row i0+kg
            ull ax, ay;
            if (kg == 0)      { ax = a00; ay = a01; }
            else if (kg == 1) { ax = a10; ay = a11; }
            else if (kg == 2) { ax = a20; ay = a21; }
            else              { ax = a30; ay = a31; }
            float2 lo = upk(ax), hi = upk(ay);
            const int row = i0 + kg;
            if (tr < 8) {
                float* up = bu + row * 16 + cb4;
                float4 u0 = *(const float4*)up;
                u0.x -= lo.x; u0.y -= lo.y; u0.z -= hi.x; u0.w -= hi.y;
                *(float4*)up = u0;
            } else {
                *(float4*)(po + (row - 32) * 16 + cb4) =
                    make_float4(lo.x, lo.y, hi.x, hi.y);
            }
        }
        __syncthreads();

        if (t < 128) {
            const int rt = t >> 2, ct = t & 3;
            const int rb = rt << 2;
            const int physc = ((ct ^ ((rt ^ (rt >> 3)) & 3)) << 2);
            float* sp0 = sS + rb * 16 + physc;
            ulonglong2 s0 = *(const ulonglong2*)(sp0);
            ulonglong2 s1 = *(const ulonglong2*)(sp0 + 16);
            ulonglong2 s2v = *(const ulonglong2*)(sp0 + 32);
            ulonglong2 s3 = *(const ulonglong2*)(sp0 + 48);
            const float* kp = B + OFF_K + rb;
            const float* up2 = bu + (ct << 2);
            #pragma unroll 8
            for (int j = 0; j < 32; j++) {
                float4 k4 = *(const float4*)kp;
                ulonglong2 u2 = *(const ulonglong2*)up2;
                fm2(s0.x,  pk1(k4.x), u2.x); fm2(s0.y,  pk1(k4.x), u2.y);
                fm2(s1.x,  pk1(k4.y), u2.x); fm2(s1.y,  pk1(k4.y), u2.y);
                fm2(s2v.x, pk1(k4.z), u2.x); fm2(s2v.y, pk1(k4.z), u2.y);
                fm2(s3.x,  pk1(k4.w), u2.x); fm2(s3.y,  pk1(k4.w), u2.y);
                kp += 128; up2 += 16;
            }
            *(ulonglong2*)(sp0)      = s0;
            *(ulonglong2*)(sp0 + 16) = s1;
            *(ulonglong2*)(sp0 + 32) = s2v;
            *(ulonglong2*)(sp0 + 48) = s3;
        } else {
            const int ii2 = (t - 128) >> 2, cq = t & 3;
            const int asw = ii2 & 7;
            ulonglong2 acc = *(const ulonglong2*)(po + ii2 * 16 + (cq << 2));
            const float* atr = B + OFF_AT + ii2 * 32;
            const float* Up = bu + (cq << 2);
            #pragma unroll
            for (int j4 = 0; j4 < 8; j4++) {
                float4 a4 = *(const float4*)(atr + ((j4 ^ asw) << 2));
                const float* u0p = Up + (j4 << 6);
                ulonglong2 U0 = *(const ulonglong2*)(u0p);
                ulonglong2 U1 = *(const ulonglong2*)(u0p + 16);
                ulonglong2 U2 = *(const ulonglong2*)(u0p + 32);
                ulonglong2 U3 = *(const ulonglong2*)(u0p + 48);
                fm2(acc.x, pk1(a4.x), U0.x); fm2(acc.y, pk1(a4.x), U0.y);
                fm2(acc.x, pk1(a4.y), U1.x); fm2(acc.y, pk1(a4.y), U1.y);
                fm2(acc.x, pk1(a4.z), U2.x); fm2(acc.y, pk1(a4.z), U2.y);
                fm2(acc.x, pk1(a4.w), U3.x); fm2(acc.y, pk1(a4.w), U3.y);
            }
            float2 f0 = upk(acc.x), f1 = upk(acc.y);
            size_t off = ((size_t)bh * LL + (size_t)ch * CC + ii2) * 128 + c0 + (cq << 2);
            *(float4*)(out + off) = make_float4(f0.x, f0.y, f1.x, f1.y);
        }
    }

    if (Sout != nullptr) {
        __syncthreads();
        size_t sb = (size_t)bh * 128 * 128;
        for (int idx = t; idx < 2048; idx += 256) {
            int r = idx >> 4, c = idx & 15;
            int phys = ((((c >> 2) ^ ((r >> 2) & 3) ^ ((r >> 5) & 3)) & 3) << 2) + (c & 3);
            Sout[sb + (size_t)r * 128 + c0 + c] = sS[r * 16 + phys];
        }
    }
}

// =====================================================================
#define P1_SMEM ((3 * CC * SDK + CC * (CC + 1) + 3 * CC) * (int)sizeof(float))
#define P2_SMEM ((4 + 2048 + 512 + 2 * BUF_F) * (int)sizeof(float))

extern "C" void kernel_launch(void* const* d_in, const int* in_sizes, int n_in,
                              void* d_out, int out_size)
{
    const float* q    = (const float*)d_in[0];
    const float* k    = (const float*)d_in[1];
    const float* v    = (const float*)d_in[2];
    const float* beta = (const float*)d_in[3];
    float* out = (float*)d_out;
    float* Sout = ((size_t)out_size >= OUT_ELEMS + S_ELEMS) ? (out + OUT_ELEMS) : nullptr;

    cudaFuncSetAttribute(phase1_kernel, cudaFuncAttributeMaxDynamicSharedMemorySize, P1_SMEM);
    cudaFuncSetAttribute(phase2_kernel, cudaFuncAttributeMaxDynamicSharedMemorySize, P2_SMEM);

    phase1_kernel<<<dim3(NCH, BHT), 256, P1_SMEM>>>(q, k, v, beta);
    phase2_kernel<<<dim3(8, BHT), 256, P2_SMEM>>>(out, Sout);
}